// round 10
// baseline (speedup 1.0000x reference)
#include <cuda_runtime.h>
#include <cuda_fp16.h>
#include <math_constants.h>
#include <cstdint>

// ---------------------------------------------------------------------------
// Problem constants
// ---------------------------------------------------------------------------
#define BB 4
#define TT 2048
#define CC 768
#define HH 768
#define MTOT (BB * TT)           // 8192
static const float QK_SCALE = 0.03608439182435161f;  // 1/sqrt(768)

// ---------------------------------------------------------------------------
// Scratch globals (operands fp16; scores fp32)
// ---------------------------------------------------------------------------
__device__ __half g_x [(size_t)MTOT * CC];
__device__ __half g_wt[(size_t)3 * CC * HH];    // W^T  [z][n][k]
__device__ __half g_q [(size_t)MTOT * HH];
__device__ __half g_k [(size_t)MTOT * HH];
__device__ __half g_v [(size_t)MTOT * HH];
__device__ __half g_vt[(size_t)BB * HH * TT];   // V^T per batch
__device__ float  g_s [(size_t)BB * TT * TT];   // raw scores (fp32)
__device__ __half g_p [(size_t)BB * TT * TT];   // softmax probs (fp16)

// ---------------------------------------------------------------------------
// GEMM config: CTA 128x128, 128 threads (4 warps 2x2), warp tile 64x64,
// fp16 m16n8k16 mma, K-chunk 64 halfs (128B rows), 2-stage cp.async,
// single-buffered ldmatrix.x4 fragments.
// KEY CHANGE: 3 CTAs/SM (launch_bounds(128,3), 2 stages x 32KB x 3 = 192KB
// smem, regs capped at 170). Chunk-boundary stalls (barrier + LDSM prime)
// were leaving the tensor pipe at 46% with only 2 resident CTAs; 3 CTAs
// give 2 spare CTAs of coverage per boundary.
// ---------------------------------------------------------------------------
#define TM 128
#define TN 128
#define TK 64
#define STAGE_BYTES (2 * 128 * 128)       // A(16KB) + B(16KB)
#define NSTAGE 2
#define SMEM_BYTES (NSTAGE * STAGE_BYTES) // 65536

__device__ __forceinline__ uint32_t smem_u32(const void* p) {
    uint32_t a;
    asm("{ .reg .u64 t; cvta.to.shared.u64 t, %1; cvt.u32.u64 %0, t; }"
        : "=r"(a) : "l"(p));
    return a;
}

__device__ __forceinline__ void cp16(uint32_t dst, const void* src) {
    asm volatile("cp.async.cg.shared.global [%0], [%1], 16;"
                 :: "r"(dst), "l"(src) : "memory");
}

__device__ __forceinline__ void ldsm_x4(uint32_t r[4], uint32_t addr) {
    asm volatile("ldmatrix.sync.aligned.m8n8.x4.shared.b16 {%0,%1,%2,%3}, [%4];"
                 : "=r"(r[0]), "=r"(r[1]), "=r"(r[2]), "=r"(r[3]) : "r"(addr));
}

__device__ __forceinline__ void mma_f16(float c[4], const uint32_t a[4],
                                        const uint32_t b0, const uint32_t b1) {
    asm volatile(
        "mma.sync.aligned.m16n8k16.row.col.f32.f16.f16.f32 "
        "{%0,%1,%2,%3}, {%4,%5,%6,%7}, {%8,%9}, {%0,%1,%2,%3};"
        : "+f"(c[0]), "+f"(c[1]), "+f"(c[2]), "+f"(c[3])
        : "r"(a[0]), "r"(a[1]), "r"(a[2]), "r"(a[3]), "r"(b0), "r"(b1));
}

// Load one K-chunk (A: 128x64h, B: 128x64h) into a stage via cp.async,
// XOR swizzle per 16B granule (8 halfs). 128 threads, 8 iters each.
__device__ __forceinline__ void load_chunk(uint32_t sA, uint32_t sB,
                                           const __half* Ag, int lda,
                                           const __half* Bg, int ldb, int tid) {
    #pragma unroll
    for (int i = 0; i < 8; i++) {
        int idx = tid + i * 128;          // 0..1023
        int row = idx >> 3, gc = idx & 7;
        uint32_t off = (uint32_t)(row * 128 + ((gc * 16) ^ ((row & 7) * 16)));
        cp16(sA + off, Ag + (size_t)row * lda + gc * 8);
        cp16(sB + off, Bg + (size_t)row * ldb + gc * 8);
    }
}

// ---------------------------------------------------------------------------
// Generic 128x128 fp16 mma.sync GEMM tile (4 warps, 64x64 warp tiles):
//   C[row0+i, col0+j] = scale * sum_k A[row0+i,k] * B[col0+j,k] (+ bias[col])
// ---------------------------------------------------------------------------
template <bool HALF_OUT>
__device__ __forceinline__ void gemm_tile(
    const __half* __restrict__ A, int lda,
    const __half* __restrict__ B, int ldb,
    void* __restrict__ Cv, int ldc,
    int row0, int col0, int K,
    const float* __restrict__ bias, float scale)
{
    extern __shared__ float smf[];
    const uint32_t sbase = smem_u32(smf);

    const int tid   = threadIdx.x;
    const int warp  = tid >> 5;
    const int lane  = tid & 31;
    const int wm    = (warp & 1) * 64;
    const int wn    = (warp >> 1) * 64;
    const int g     = lane >> 2;
    const int t     = lane & 3;

    const __half* Arow = A + (size_t)row0 * lda;
    const __half* Brow = B + (size_t)col0 * ldb;
    const int NC = K / TK;

    float acc[4][8][4];
    #pragma unroll
    for (int mi = 0; mi < 4; mi++)
        #pragma unroll
        for (int ni = 0; ni < 8; ni++)
            #pragma unroll
            for (int j = 0; j < 4; j++) acc[mi][ni][j] = 0.0f;

    uint32_t stA[NSTAGE], stB[NSTAGE];
    #pragma unroll
    for (int s = 0; s < NSTAGE; s++) {
        stA[s] = sbase + (uint32_t)(s * STAGE_BYTES);
        stB[s] = stA[s] + (uint32_t)(128 * 128);
    }

    // Prologue: chunk 0 -> stage 0
    load_chunk(stA[0], stB[0], Arow, lda, Brow, ldb, tid);
    asm volatile("cp.async.commit_group;" ::: "memory");

    const uint32_t aRow = (uint32_t)(wm + (lane & 15)) * 128;
    const uint32_t bRow = (uint32_t)(wn + (lane & 15)) * 128;
    const uint32_t cHi  = (uint32_t)(lane >> 4) * 16;
    const uint32_t xr   = (uint32_t)(lane & 7) * 16;

    #pragma unroll 1
    for (int c = 0; c < NC; c++) {
        asm volatile("cp.async.wait_group 0;" ::: "memory");
        __syncthreads();

        const int cn = c + 1;
        if (cn < NC)
            load_chunk(stA[cn & 1], stB[cn & 1],
                       Arow + cn * TK, lda, Brow + cn * TK, ldb, tid);
        asm volatile("cp.async.commit_group;" ::: "memory");

        const uint32_t aB = stA[c & 1] + aRow;
        const uint32_t bB = stB[c & 1] + bRow;

        #pragma unroll
        for (int ks = 0; ks < 4; ks++) {
            const uint32_t koff = ((uint32_t)(2 * ks) * 16 + cHi) ^ xr;
            uint32_t a[4][4], bf[4][4];
            #pragma unroll
            for (int mi = 0; mi < 4; mi++)
                ldsm_x4(a[mi], aB + (uint32_t)mi * 2048 + koff);
            #pragma unroll
            for (int p = 0; p < 4; p++)
                ldsm_x4(bf[p], bB + (uint32_t)p * 2048 + koff);
            #pragma unroll
            for (int mi = 0; mi < 4; mi++)
                #pragma unroll
                for (int p = 0; p < 4; p++) {
                    mma_f16(acc[mi][2 * p],     a[mi], bf[p][0], bf[p][2]);
                    mma_f16(acc[mi][2 * p + 1], a[mi], bf[p][1], bf[p][3]);
                }
        }
        __syncthreads();  // stage consumed before next iter overwrites it
    }

    // Epilogue
    #pragma unroll
    for (int mi = 0; mi < 4; mi++) {
        const int r0 = row0 + wm + mi * 16 + g;
        #pragma unroll
        for (int ni = 0; ni < 8; ni++) {
            const int ccol = col0 + wn + ni * 8 + 2 * t;
            float v0 = acc[mi][ni][0] * scale;
            float v1 = acc[mi][ni][1] * scale;
            float v2 = acc[mi][ni][2] * scale;
            float v3 = acc[mi][ni][3] * scale;
            if (bias) {
                float b0 = bias[ccol], b1 = bias[ccol + 1];
                v0 += b0; v1 += b1; v2 += b0; v3 += b1;
            }
            if (HALF_OUT) {
                __half* C = (__half*)Cv;
                *(__half2*)(C + (size_t)r0 * ldc + ccol) = __floats2half2_rn(v0, v1);
                *(__half2*)(C + (size_t)(r0 + 8) * ldc + ccol) = __floats2half2_rn(v2, v3);
            } else {
                float* C = (float*)Cv;
                *(float2*)(C + (size_t)r0 * ldc + ccol) = make_float2(v0, v1);
                *(float2*)(C + (size_t)(r0 + 8) * ldc + ccol) = make_float2(v2, v3);
            }
        }
    }
}

// ---------------------------------------------------------------------------
// GEMM wrappers
// ---------------------------------------------------------------------------
__global__ __launch_bounds__(128, 3) void qkv_mma(
    const float* __restrict__ bq, const float* __restrict__ bk,
    const float* __restrict__ bv)
{
    const int z = blockIdx.z;
    const float* bias = (z == 0) ? bq : (z == 1) ? bk : bv;
    __half* out = (z == 0) ? g_q : (z == 1) ? g_k : g_v;
    const __half* B = g_wt + (size_t)z * CC * HH;
    gemm_tile<true>(g_x, CC, B, CC, out, HH,
                    blockIdx.y * TM, blockIdx.x * TN, CC, bias, 1.0f);
}

// Compact lower-triangular grid: 136 live tiles per batch, 544 CTAs total.
__global__ __launch_bounds__(128, 3) void scores_mma()
{
    const int b = blockIdx.x / 136;
    const int tidx = blockIdx.x % 136;
    // invert triangular index: largest mi with mi*(mi+1)/2 <= tidx
    int mi = (int)((sqrtf(8.0f * (float)tidx + 1.0f) - 1.0f) * 0.5f);
    while ((mi + 1) * (mi + 2) / 2 <= tidx) mi++;
    while (mi * (mi + 1) / 2 > tidx) mi--;
    const int nj = tidx - mi * (mi + 1) / 2;

    const __half* q = g_q + (size_t)b * TT * HH;
    const __half* k = g_k + (size_t)b * TT * HH;
    gemm_tile<false>(q, HH, k, HH, g_s + (size_t)b * TT * TT, TT,
                     mi * TM, nj * TN, HH, nullptr, QK_SCALE);
}

__global__ __launch_bounds__(128, 3) void pv_mma(float* __restrict__ out)
{
    const int nj = blockIdx.x, b = blockIdx.z;
    const int mi = (int)gridDim.y - 1 - (int)blockIdx.y;  // longest rows first
    const __half* P = g_p + (size_t)b * TT * TT;
    const __half* Vt = g_vt + (size_t)b * HH * TT;
    gemm_tile<false>(P, TT, Vt, TT, out + (size_t)b * TT * HH, HH,
                     mi * TM, nj * TN, (mi + 1) * TM, nullptr, 1.0f);
}

// ---------------------------------------------------------------------------
// Convert x to fp16 (8 elements/thread)
// ---------------------------------------------------------------------------
__global__ __launch_bounds__(256) void conv_x_kernel(const float* __restrict__ x)
{
    size_t i = (size_t)blockIdx.x * 256 + threadIdx.x;
    const float4* p = (const float4*)x + 2 * i;
    float4 v0 = p[0], v1 = p[1];
    __half2 h[4];
    h[0] = __floats2half2_rn(v0.x, v0.y);
    h[1] = __floats2half2_rn(v0.z, v0.w);
    h[2] = __floats2half2_rn(v1.x, v1.y);
    h[3] = __floats2half2_rn(v1.z, v1.w);
    ((uint4*)g_x)[i] = *(uint4*)h;
}

// ---------------------------------------------------------------------------
// Transposes (to fp16)
// ---------------------------------------------------------------------------
__global__ void transpose_w_kernel(const float* __restrict__ Wq,
                                   const float* __restrict__ Wk,
                                   const float* __restrict__ Wv)
{
    const int z = blockIdx.z;
    const float* src = (z == 0) ? Wq : (z == 1) ? Wk : Wv;
    __half* dst = g_wt + (size_t)z * CC * HH;
    __shared__ float t[32][33];
    const int c0 = blockIdx.x * 32, r0 = blockIdx.y * 32;
    const int tx = threadIdx.x, ty = threadIdx.y;
    #pragma unroll
    for (int i = 0; i < 4; i++)
        t[ty + 8 * i][tx] = src[(size_t)(r0 + ty + 8 * i) * HH + c0 + tx];
    __syncthreads();
    #pragma unroll
    for (int i = 0; i < 4; i++)
        dst[(size_t)(c0 + ty + 8 * i) * CC + r0 + tx] =
            __float2half_rn(t[tx][ty + 8 * i]);
}

__global__ void transpose_v_kernel()
{
    const int b = blockIdx.z;
    const __half* src = g_v + (size_t)b * TT * HH;
    __half* dst = g_vt + (size_t)b * HH * TT;
    __shared__ float t[32][33];
    const int c0 = blockIdx.x * 32, r0 = blockIdx.y * 32;
    const int tx = threadIdx.x, ty = threadIdx.y;
    #pragma unroll
    for (int i = 0; i < 4; i++)
        t[ty + 8 * i][tx] = __half2float(src[(size_t)(r0 + ty + 8 * i) * HH + c0 + tx]);
    __syncthreads();
    #pragma unroll
    for (int i = 0; i < 4; i++)
        dst[(size_t)(c0 + ty + 8 * i) * TT + r0 + tx] =
            __float2half_rn(t[tx][ty + 8 * i]);
}

// ---------------------------------------------------------------------------
// Causal row softmax: read fp32 g_s, write fp16 probs to g_p
// ---------------------------------------------------------------------------
__global__ __launch_bounds__(256) void softmax_kernel()
{
    const int row = blockIdx.x;
    const int b = row / TT, i = row % TT;
    const float* S = g_s + (size_t)b * TT * TT + (size_t)i * TT;
    __half* P = g_p + (size_t)b * TT * TT + (size_t)i * TT;
    const int n = i + 1;
    const int tid = threadIdx.x;
    const int base = tid * 8;

    float4 u0 = ((const float4*)S)[tid * 2];
    float4 u1 = ((const float4*)S)[tid * 2 + 1];
    float vals[8] = {u0.x, u0.y, u0.z, u0.w, u1.x, u1.y, u1.z, u1.w};
    #pragma unroll
    for (int jj = 0; jj < 8; jj++)
        if (base + jj >= n) vals[jj] = -CUDART_INF_F;

    __shared__ float red[256];
    float m = vals[0];
    #pragma unroll
    for (int jj = 1; jj < 8; jj++) m = fmaxf(m, vals[jj]);
    red[tid] = m;
    __syncthreads();
    #pragma unroll
    for (int s = 128; s > 0; s >>= 1) {
        if (tid < s) red[tid] = fmaxf(red[tid], red[tid + s]);
        __syncthreads();
    }
    m = red[0];
    __syncthreads();

    float e[8];
    float sum = 0.0f;
    #pragma unroll
    for (int jj = 0; jj < 8; jj++) {
        e[jj] = (vals[jj] == -CUDART_INF_F) ? 0.0f : __expf(vals[jj] - m);
        sum += e[jj];
    }
    red[tid] = sum;
    __syncthreads();
    #pragma unroll
    for (int s = 128; s > 0; s >>= 1) {
        if (tid < s) red[tid] += red[tid + s];
        __syncthreads();
    }
    const float inv = 1.0f / red[0];

    __half2 h[4];
    #pragma unroll
    for (int jj = 0; jj < 4; jj++)
        h[jj] = __floats2half2_rn(e[2 * jj] * inv, e[2 * jj + 1] * inv);
    ((uint4*)P)[tid] = *(uint4*)h;
}

// ---------------------------------------------------------------------------
// Launch (scores_mma kept in ncu's profiled slot)
// ---------------------------------------------------------------------------
extern "C" void kernel_launch(void* const* d_in, const int* in_sizes, int n_in,
                              void* d_out, int out_size)
{
    const float* x  = (const float*)d_in[0];
    const float* Wq = (const float*)d_in[1];
    const float* bq = (const float*)d_in[2];
    const float* Wk = (const float*)d_in[3];
    const float* bk = (const float*)d_in[4];
    const float* Wv = (const float*)d_in[5];
    const float* bv = (const float*)d_in[6];
    float* out = (float*)d_out;

    cudaFuncSetAttribute(qkv_mma, cudaFuncAttributeMaxDynamicSharedMemorySize, SMEM_BYTES);
    cudaFuncSetAttribute(scores_mma, cudaFuncAttributeMaxDynamicSharedMemorySize, SMEM_BYTES);
    cudaFuncSetAttribute(pv_mma, cudaFuncAttributeMaxDynamicSharedMemorySize, SMEM_BYTES);

    conv_x_kernel<<<MTOT * CC / (256 * 8), 256>>>(x);
    transpose_w_kernel<<<dim3(HH / 32, CC / 32, 3), dim3(32, 8)>>>(Wq, Wk, Wv);
    qkv_mma<<<dim3(HH / TN, MTOT / TM, 3), 128, SMEM_BYTES>>>(bq, bk, bv);
    scores_mma<<<dim3(136 * BB), 128, SMEM_BYTES>>>();
    transpose_v_kernel<<<dim3(HH / 32, TT / 32, BB), dim3(32, 8)>>>();
    softmax_kernel<<<dim3(BB * TT), 256>>>();
    pv_mma<<<dim3(HH / TN, TT / TM, BB), 128, SMEM_BYTES>>>(out);
}

// round 11
// speedup vs baseline: 1.1717x; 1.1717x over previous
#include <cuda_runtime.h>
#include <cuda_fp16.h>
#include <math_constants.h>
#include <cstdint>

// ---------------------------------------------------------------------------
// Problem constants
// ---------------------------------------------------------------------------
#define BB 4
#define TT 2048
#define CC 768
#define HH 768
#define MTOT (BB * TT)           // 8192
static const float QK_SCALE = 0.03608439182435161f;  // 1/sqrt(768)

// ---------------------------------------------------------------------------
// Scratch globals (operands fp16; scores fp32)
// ---------------------------------------------------------------------------
__device__ __half g_x [(size_t)MTOT * CC];
__device__ __half g_wt[(size_t)3 * CC * HH];    // W^T  [z][n][k]
__device__ __half g_q [(size_t)MTOT * HH];
__device__ __half g_k [(size_t)MTOT * HH];
__device__ __half g_v [(size_t)MTOT * HH];      // [t][h] per batch (no transpose)
__device__ float  g_s [(size_t)BB * TT * TT];   // raw scores (fp32)
__device__ __half g_p [(size_t)BB * TT * TT];   // softmax probs (fp16)

// ---------------------------------------------------------------------------
// GEMM config: CTA 128x128, 128 threads (4 warps 2x2), warp tile 64x64,
// fp16 m16n8k16 mma, K-chunk 64, 3-stage cp.async, ldmatrix.x4 fragments.
// At the mma.sync throughput ceiling (tensor ~46% of tcgen05-rate counter);
// this round only removes overhead: pv consumes V [t][h] directly via
// ldmatrix.trans (transpose_v kernel deleted).
// 3 stages * 32KB = 96KB -> 2 CTAs/SM.
// ---------------------------------------------------------------------------
#define TM 128
#define TN 128
#define TK 64
#define STAGE_BYTES (2 * 128 * 128)       // A(16KB) + B(16KB)
#define NSTAGE 3
#define SMEM_BYTES (NSTAGE * STAGE_BYTES) // 98304

__device__ __forceinline__ uint32_t smem_u32(const void* p) {
    uint32_t a;
    asm("{ .reg .u64 t; cvta.to.shared.u64 t, %1; cvt.u32.u64 %0, t; }"
        : "=r"(a) : "l"(p));
    return a;
}

__device__ __forceinline__ void cp16(uint32_t dst, const void* src) {
    asm volatile("cp.async.cg.shared.global [%0], [%1], 16;"
                 :: "r"(dst), "l"(src) : "memory");
}

__device__ __forceinline__ void ldsm_x4(uint32_t r[4], uint32_t addr) {
    asm volatile("ldmatrix.sync.aligned.m8n8.x4.shared.b16 {%0,%1,%2,%3}, [%4];"
                 : "=r"(r[0]), "=r"(r[1]), "=r"(r[2]), "=r"(r[3]) : "r"(addr));
}

__device__ __forceinline__ void ldsm_x4_t(uint32_t r[4], uint32_t addr) {
    asm volatile("ldmatrix.sync.aligned.m8n8.x4.trans.shared.b16 {%0,%1,%2,%3}, [%4];"
                 : "=r"(r[0]), "=r"(r[1]), "=r"(r[2]), "=r"(r[3]) : "r"(addr));
}

__device__ __forceinline__ void mma_f16(float c[4], const uint32_t a[4],
                                        const uint32_t b0, const uint32_t b1) {
    asm volatile(
        "mma.sync.aligned.m16n8k16.row.col.f32.f16.f16.f32 "
        "{%0,%1,%2,%3}, {%4,%5,%6,%7}, {%8,%9}, {%0,%1,%2,%3};"
        : "+f"(c[0]), "+f"(c[1]), "+f"(c[2]), "+f"(c[3])
        : "r"(a[0]), "r"(a[1]), "r"(a[2]), "r"(a[3]), "r"(b0), "r"(b1));
}

// ---------------------------------------------------------------------------
// Generic 128x128 fp16 mma.sync GEMM tile.
// TRANSB=false: B is [n][k] fp16 (NT), 128B rows in smem.
// TRANSB=true : B is [k][n] fp16 (V layout), 256B rows in smem, trans-LDSM.
// ---------------------------------------------------------------------------
template <bool HALF_OUT, bool TRANSB>
__device__ __forceinline__ void gemm_tile(
    const __half* __restrict__ A, int lda,
    const __half* __restrict__ B, int ldb,   // TRANSB: row stride over k
    void* __restrict__ Cv, int ldc,
    int row0, int col0, int K,
    const float* __restrict__ bias, float scale)
{
    extern __shared__ float smf[];
    const uint32_t sbase = smem_u32(smf);

    const int tid   = threadIdx.x;
    const int warp  = tid >> 5;
    const int lane  = tid & 31;
    const int wm    = (warp & 1) * 64;
    const int wn    = (warp >> 1) * 64;
    const int g     = lane >> 2;
    const int t     = lane & 3;

    const __half* Arow = A + (size_t)row0 * lda;
    // TRANSB: B rows are k, columns are n; offset columns by col0.
    const __half* Brow = TRANSB ? (B + col0) : (B + (size_t)col0 * ldb);
    const int NC = K / TK;

    float acc[4][8][4];
    #pragma unroll
    for (int mi = 0; mi < 4; mi++)
        #pragma unroll
        for (int ni = 0; ni < 8; ni++)
            #pragma unroll
            for (int j = 0; j < 4; j++) acc[mi][ni][j] = 0.0f;

    uint32_t stA[NSTAGE], stB[NSTAGE];
    #pragma unroll
    for (int s = 0; s < NSTAGE; s++) {
        stA[s] = sbase + (uint32_t)(s * STAGE_BYTES);
        stB[s] = stA[s] + (uint32_t)(128 * 128);
    }

    // -- chunk loader -------------------------------------------------------
    auto load_chunk = [&](uint32_t sA, uint32_t sB, int c) {
        const __half* Ag = Arow + c * TK;
        #pragma unroll
        for (int i = 0; i < 8; i++) {            // A: 128 rows x 8 granules
            int idx = tid + i * 128;
            int row = idx >> 3, gc = idx & 7;
            uint32_t off = (uint32_t)(row * 128 + ((gc * 16) ^ ((row & 7) * 16)));
            cp16(sA + off, Ag + (size_t)row * lda + gc * 8);
        }
        if (TRANSB) {
            const __half* Bg = Brow + (size_t)c * TK * ldb;
            #pragma unroll
            for (int i = 0; i < 8; i++) {        // B: 64 k-rows x 16 granules
                int idx = tid + i * 128;
                int row = idx >> 4, gc = idx & 15;
                uint32_t off = (uint32_t)(row * 256 + ((gc * 16) ^ ((row & 7) * 16)));
                cp16(sB + off, Bg + (size_t)row * ldb + gc * 8);
            }
        } else {
            const __half* Bg = Brow + c * TK;
            #pragma unroll
            for (int i = 0; i < 8; i++) {        // B: 128 n-rows x 8 granules
                int idx = tid + i * 128;
                int row = idx >> 3, gc = idx & 7;
                uint32_t off = (uint32_t)(row * 128 + ((gc * 16) ^ ((row & 7) * 16)));
                cp16(sB + off, Bg + (size_t)row * ldb + gc * 8);
            }
        }
    };

    #pragma unroll
    for (int s = 0; s < NSTAGE - 1; s++) {
        if (s < NC) load_chunk(stA[s], stB[s], s);
        asm volatile("cp.async.commit_group;" ::: "memory");
    }

    // Fragment addressing constants
    const uint32_t aRow = (uint32_t)(wm + (lane & 15)) * 128;
    const uint32_t bRow = (uint32_t)(wn + (lane & 15)) * 128;   // NT path
    const uint32_t cHi  = (uint32_t)(lane >> 4) * 16;
    const uint32_t xr   = (uint32_t)(lane & 7) * 16;
    // TRANSB path: lane row within chunk = lane&15; per-p h-granule offset
    const uint32_t vRowB = (uint32_t)(lane & 15) * 256;
    uint32_t hx[4];
    #pragma unroll
    for (int p = 0; p < 4; p++)
        hx[p] = (uint32_t)((((wn >> 3) + 2 * p + (lane >> 4)) * 16) ^ ((lane & 7) * 16));

    #pragma unroll 1
    for (int c = 0; c < NC; c++) {
        asm volatile("cp.async.wait_group %0;" :: "n"(NSTAGE - 2) : "memory");
        __syncthreads();

        const int cn = c + NSTAGE - 1;
        if (cn < NC)
            load_chunk(stA[cn % NSTAGE], stB[cn % NSTAGE], cn);
        asm volatile("cp.async.commit_group;" ::: "memory");

        const int s = c % NSTAGE;
        const uint32_t aB = stA[s] + aRow;

        #pragma unroll
        for (int ks = 0; ks < 4; ks++) {
            uint32_t a[4][4], bf[4][4];
            const uint32_t koff = ((uint32_t)(2 * ks) * 16 + cHi) ^ xr;
            #pragma unroll
            for (int mi = 0; mi < 4; mi++)
                ldsm_x4(a[mi], aB + (uint32_t)mi * 2048 + koff);

            if (TRANSB) {
                const uint32_t bB = stB[s] + (uint32_t)ks * 4096 + vRowB;
                #pragma unroll
                for (int p = 0; p < 4; p++)
                    ldsm_x4_t(bf[p], bB + hx[p]);
                #pragma unroll
                for (int mi = 0; mi < 4; mi++)
                    #pragma unroll
                    for (int p = 0; p < 4; p++) {
                        mma_f16(acc[mi][2 * p],     a[mi], bf[p][0], bf[p][1]);
                        mma_f16(acc[mi][2 * p + 1], a[mi], bf[p][2], bf[p][3]);
                    }
            } else {
                const uint32_t bB = stB[s] + bRow;
                #pragma unroll
                for (int p = 0; p < 4; p++)
                    ldsm_x4(bf[p], bB + (uint32_t)p * 2048 + koff);
                #pragma unroll
                for (int mi = 0; mi < 4; mi++)
                    #pragma unroll
                    for (int p = 0; p < 4; p++) {
                        mma_f16(acc[mi][2 * p],     a[mi], bf[p][0], bf[p][2]);
                        mma_f16(acc[mi][2 * p + 1], a[mi], bf[p][1], bf[p][3]);
                    }
            }
        }
    }

    // Epilogue
    #pragma unroll
    for (int mi = 0; mi < 4; mi++) {
        const int r0 = row0 + wm + mi * 16 + g;
        #pragma unroll
        for (int ni = 0; ni < 8; ni++) {
            const int ccol = col0 + wn + ni * 8 + 2 * t;
            float v0 = acc[mi][ni][0] * scale;
            float v1 = acc[mi][ni][1] * scale;
            float v2 = acc[mi][ni][2] * scale;
            float v3 = acc[mi][ni][3] * scale;
            if (bias) {
                float b0 = bias[ccol], b1 = bias[ccol + 1];
                v0 += b0; v1 += b1; v2 += b0; v3 += b1;
            }
            if (HALF_OUT) {
                __half* C = (__half*)Cv;
                *(__half2*)(C + (size_t)r0 * ldc + ccol) = __floats2half2_rn(v0, v1);
                *(__half2*)(C + (size_t)(r0 + 8) * ldc + ccol) = __floats2half2_rn(v2, v3);
            } else {
                float* C = (float*)Cv;
                *(float2*)(C + (size_t)r0 * ldc + ccol) = make_float2(v0, v1);
                *(float2*)(C + (size_t)(r0 + 8) * ldc + ccol) = make_float2(v2, v3);
            }
        }
    }
}

// ---------------------------------------------------------------------------
// GEMM wrappers
// ---------------------------------------------------------------------------
__global__ __launch_bounds__(128, 2) void qkv_mma(
    const float* __restrict__ bq, const float* __restrict__ bk,
    const float* __restrict__ bv)
{
    const int z = blockIdx.z;
    const float* bias = (z == 0) ? bq : (z == 1) ? bk : bv;
    __half* out = (z == 0) ? g_q : (z == 1) ? g_k : g_v;
    const __half* B = g_wt + (size_t)z * CC * HH;
    gemm_tile<true, false>(g_x, CC, B, CC, out, HH,
                           blockIdx.y * TM, blockIdx.x * TN, CC, bias, 1.0f);
}

// Compact lower-triangular grid: 136 live tiles per batch, 544 CTAs total.
__global__ __launch_bounds__(128, 2) void scores_mma()
{
    const int b = blockIdx.x / 136;
    const int tidx = blockIdx.x % 136;
    int mi = (int)((sqrtf(8.0f * (float)tidx + 1.0f) - 1.0f) * 0.5f);
    while ((mi + 1) * (mi + 2) / 2 <= tidx) mi++;
    while (mi * (mi + 1) / 2 > tidx) mi--;
    const int nj = tidx - mi * (mi + 1) / 2;

    const __half* q = g_q + (size_t)b * TT * HH;
    const __half* k = g_k + (size_t)b * TT * HH;
    gemm_tile<false, false>(q, HH, k, HH, g_s + (size_t)b * TT * TT, TT,
                            mi * TM, nj * TN, HH, nullptr, QK_SCALE);
}

__global__ __launch_bounds__(128, 2) void pv_mma(float* __restrict__ out)
{
    const int nj = blockIdx.x, b = blockIdx.z;
    const int mi = (int)gridDim.y - 1 - (int)blockIdx.y;  // longest rows first
    const __half* P = g_p + (size_t)b * TT * TT;
    const __half* V = g_v + (size_t)b * TT * HH;          // [t][h]
    gemm_tile<false, true>(P, TT, V, HH, out + (size_t)b * TT * HH, HH,
                           mi * TM, nj * TN, (mi + 1) * TM, nullptr, 1.0f);
}

// ---------------------------------------------------------------------------
// Convert x to fp16 (8 elements/thread)
// ---------------------------------------------------------------------------
__global__ __launch_bounds__(256) void conv_x_kernel(const float* __restrict__ x)
{
    size_t i = (size_t)blockIdx.x * 256 + threadIdx.x;
    const float4* p = (const float4*)x + 2 * i;
    float4 v0 = p[0], v1 = p[1];
    __half2 h[4];
    h[0] = __floats2half2_rn(v0.x, v0.y);
    h[1] = __floats2half2_rn(v0.z, v0.w);
    h[2] = __floats2half2_rn(v1.x, v1.y);
    h[3] = __floats2half2_rn(v1.z, v1.w);
    ((uint4*)g_x)[i] = *(uint4*)h;
}

// ---------------------------------------------------------------------------
// W transpose (to fp16)
// ---------------------------------------------------------------------------
__global__ void transpose_w_kernel(const float* __restrict__ Wq,
                                   const float* __restrict__ Wk,
                                   const float* __restrict__ Wv)
{
    const int z = blockIdx.z;
    const float* src = (z == 0) ? Wq : (z == 1) ? Wk : Wv;
    __half* dst = g_wt + (size_t)z * CC * HH;
    __shared__ float t[32][33];
    const int c0 = blockIdx.x * 32, r0 = blockIdx.y * 32;
    const int tx = threadIdx.x, ty = threadIdx.y;
    #pragma unroll
    for (int i = 0; i < 4; i++)
        t[ty + 8 * i][tx] = src[(size_t)(r0 + ty + 8 * i) * HH + c0 + tx];
    __syncthreads();
    #pragma unroll
    for (int i = 0; i < 4; i++)
        dst[(size_t)(c0 + ty + 8 * i) * CC + r0 + tx] =
            __float2half_rn(t[tx][ty + 8 * i]);
}

// ---------------------------------------------------------------------------
// Causal row softmax: only the live tile range [0, Bnd) per row.
// Bnd = ((i>>7)+1)*128 — exactly the region pv reads.
// ---------------------------------------------------------------------------
__global__ __launch_bounds__(256) void softmax_kernel()
{
    const int row = blockIdx.x;
    const int b = row / TT, i = row % TT;
    const float* S = g_s + (size_t)b * TT * TT + (size_t)i * TT;
    __half* P = g_p + (size_t)b * TT * TT + (size_t)i * TT;
    const int n = i + 1;
    const int Bnd = ((i >> 7) + 1) << 7;
    const int tid = threadIdx.x;
    const int base = tid * 8;
    const bool active = base < Bnd;

    float vals[8];
    #pragma unroll
    for (int jj = 0; jj < 8; jj++) vals[jj] = -CUDART_INF_F;
    if (active) {
        float4 u0 = ((const float4*)S)[tid * 2];
        float4 u1 = ((const float4*)S)[tid * 2 + 1];
        vals[0] = u0.x; vals[1] = u0.y; vals[2] = u0.z; vals[3] = u0.w;
        vals[4] = u1.x; vals[5] = u1.y; vals[6] = u1.z; vals[7] = u1.w;
        #pragma unroll
        for (int jj = 0; jj < 8; jj++)
            if (base + jj >= n) vals[jj] = -CUDART_INF_F;
    }

    __shared__ float red[256];
    float m = vals[0];
    #pragma unroll
    for (int jj = 1; jj < 8; jj++) m = fmaxf(m, vals[jj]);
    red[tid] = m;
    __syncthreads();
    #pragma unroll
    for (int s = 128; s > 0; s >>= 1) {
        if (tid < s) red[tid] = fmaxf(red[tid], red[tid + s]);
        __syncthreads();
    }
    m = red[0];
    __syncthreads();

    float e[8];
    float sum = 0.0f;
    #pragma unroll
    for (int jj = 0; jj < 8; jj++) {
        e[jj] = (vals[jj] == -CUDART_INF_F) ? 0.0f : __expf(vals[jj] - m);
        sum += e[jj];
    }
    red[tid] = sum;
    __syncthreads();
    #pragma unroll
    for (int s = 128; s > 0; s >>= 1) {
        if (tid < s) red[tid] += red[tid + s];
        __syncthreads();
    }
    const float inv = 1.0f / red[0];

    if (active) {
        __half2 h[4];
        #pragma unroll
        for (int jj = 0; jj < 4; jj++)
            h[jj] = __floats2half2_rn(e[2 * jj] * inv, e[2 * jj + 1] * inv);
        ((uint4*)P)[tid] = *(uint4*)h;
    }
}

// ---------------------------------------------------------------------------
// Launch (scores_mma kept in ncu's profiled slot)
// ---------------------------------------------------------------------------
extern "C" void kernel_launch(void* const* d_in, const int* in_sizes, int n_in,
                              void* d_out, int out_size)
{
    const float* x  = (const float*)d_in[0];
    const float* Wq = (const float*)d_in[1];
    const float* bq = (const float*)d_in[2];
    const float* Wk = (const float*)d_in[3];
    const float* bk = (const float*)d_in[4];
    const float* Wv = (const float*)d_in[5];
    const float* bv = (const float*)d_in[6];
    float* out = (float*)d_out;

    cudaFuncSetAttribute(qkv_mma, cudaFuncAttributeMaxDynamicSharedMemorySize, SMEM_BYTES);
    cudaFuncSetAttribute(scores_mma, cudaFuncAttributeMaxDynamicSharedMemorySize, SMEM_BYTES);
    cudaFuncSetAttribute(pv_mma, cudaFuncAttributeMaxDynamicSharedMemorySize, SMEM_BYTES);

    conv_x_kernel<<<MTOT * CC / (256 * 8), 256>>>(x);
    transpose_w_kernel<<<dim3(HH / 32, CC / 32, 3), dim3(32, 8)>>>(Wq, Wk, Wv);
    qkv_mma<<<dim3(HH / TN, MTOT / TM, 3), 128, SMEM_BYTES>>>(bq, bk, bv);
    scores_mma<<<dim3(136 * BB), 128, SMEM_BYTES>>>();
    softmax_kernel<<<dim3(BB * TT), 256>>>();
    pv_mma<<<dim3(HH / TN, TT / TM, BB), 128, SMEM_BYTES>>>(out);
}